// round 16
// baseline (speedup 1.0000x reference)
#include <cuda_runtime.h>
#include <cuda_bf16.h>
#include <cuda_fp16.h>
#include <cuda_fp8.h>
#include <cstdint>

#define NROWS 4096
#define DIM   512
#define NCLS  100000
#define NCLSP 100096         // padded rows in g_WB8 (pad zero-filled)
#define NBM   32
#define NBN   782            // ceil(100000/128)
#define NTILES (NBM * NBN)   // 25024
#define GRID  296            // 2 CTAs per SM
#define THREADS 256
#define S_SCALE 30.0f
#define MARGIN  0.4f
#define XS 8.0f              // fp8 scale for xn
#define WS 32.0f             // fp8 scale for W
#define EXPS (S_SCALE / (XS * WS))
#define LOG2E 1.4426950408889634f

// ---------------- scratch (module-static device memory: allowed) ------------
__device__ __align__(128) uint8_t g_WB8[(size_t)NCLSP * DIM];  // e4m3 W*32 (+pad)
__device__ __align__(128) uint8_t g_xn8[(size_t)NROWS * DIM];  // e4m3 xn*8
__device__ float g_rowsum[NROWS];
__device__ float g_target[NROWS];
__device__ int   g_done;

// ---------------- PTX helpers (sm_80/89-era, safe on sm_103) ----------------
__device__ __forceinline__ uint32_t smem_u32(const void* p) {
    uint32_t a;
    asm("{ .reg .u64 t; cvta.to.shared.u64 t, %1; cvt.u32.u64 %0, t; }" : "=r"(a) : "l"(p));
    return a;
}
#define CP_ASYNC16(dst, src) \
    asm volatile("cp.async.cg.shared.global [%0], [%1], 16;" :: "r"(dst), "l"(src) : "memory")
#define CP_COMMIT()  asm volatile("cp.async.commit_group;" ::: "memory")
#define CP_WAIT0()   asm volatile("cp.async.wait_group 0;" ::: "memory")

__device__ __forceinline__ void ldsm4(uint32_t* r, uint32_t addr) {
    asm volatile("ldmatrix.sync.aligned.m8n8.x4.shared.b16 {%0,%1,%2,%3}, [%4];"
                 : "=r"(r[0]), "=r"(r[1]), "=r"(r[2]), "=r"(r[3]) : "r"(addr));
}
__device__ __forceinline__ uint32_t ldg32(const uint8_t* p) {
    uint32_t r;
    asm volatile("ld.global.nc.u32 %0, [%1];" : "=r"(r) : "l"(p));
    return r;
}
__device__ __forceinline__ void mma_fp8_h(uint32_t* c, const uint32_t* a,
                                          uint32_t b0, uint32_t b1) {
    asm volatile("mma.sync.aligned.m16n8k32.row.col.f16.e4m3.e4m3.f16 "
                 "{%0,%1}, {%2,%3,%4,%5}, {%6,%7}, {%0,%1};"
                 : "+r"(c[0]), "+r"(c[1])
                 : "r"(a[0]), "r"(a[1]), "r"(a[2]), "r"(a[3]), "r"(b0), "r"(b1));
}
__device__ __forceinline__ uint32_t h2ex2(uint32_t x) {
    uint32_t r;
    asm("ex2.approx.f16x2 %0, %1;" : "=r"(r) : "r"(x));
    return r;
}
__device__ __forceinline__ uint32_t pack4_e4m3(float a0, float a1, float a2, float a3) {
    __nv_fp8x2_e4m3 lo(make_float2(a0, a1));
    __nv_fp8x2_e4m3 hi(make_float2(a2, a3));
    return (uint32_t)lo.__x | ((uint32_t)hi.__x << 16);
}
__device__ __forceinline__ float2 h2f2(uint32_t r) {
    return __half22float2(*reinterpret_cast<__half2*>(&r));
}

// ---------------- tiling -------------------------------------------------------
#define BM 128
#define BN 128
#define APITCH 528           // A row pitch bytes; 132 words == 4 mod 32
#define A_BYTES (BM * APITCH)          // 67584
#define SMEM_BYTES A_BYTES             // B never touches SMEM

// ======================= kernel 1: prep ======================================
__device__ __forceinline__ float block_reduce_128(float v, float* sbuf, int tid) {
    #pragma unroll
    for (int o = 16; o > 0; o >>= 1) v += __shfl_xor_sync(0xffffffffu, v, o);
    if ((tid & 31) == 0) sbuf[tid >> 5] = v;
    __syncthreads();
    float r = sbuf[0] + sbuf[1] + sbuf[2] + sbuf[3];
    __syncthreads();
    return r;
}

__global__ void prep_kernel(const float* __restrict__ x,
                            const int* __restrict__ labels_raw,
                            const float* __restrict__ W) {
    __shared__ float sbuf[4];
    const int tid = threadIdx.x;
    if (blockIdx.x < NROWS) {
        const int row = blockIdx.x;
        const float* xr = x + (size_t)row * DIM;
        float v[4]; float ss = 0.f;
        #pragma unroll
        for (int j = 0; j < 4; j++) { v[j] = xr[tid + 128*j]; ss += v[j]*v[j]; }
        ss = block_reduce_128(ss, sbuf, tid);
        float inv = rsqrtf(ss);
        #pragma unroll
        for (int j = 0; j < 4; j++)
            g_xn8[(size_t)row * DIM + tid + 128*j] =
                __nv_fp8_e4m3(v[j] * inv * XS).__x;

        bool is64 = (labels_raw[1] == 0 && labels_raw[3] == 0 &&
                     labels_raw[5] == 0 && labels_raw[7] == 0);
        int lab = is64 ? labels_raw[2*row] : labels_raw[row];
        const float* w = W + (size_t)lab * DIM;
        float dot = 0.f;
        #pragma unroll
        for (int j = 0; j < 4; j++) dot += v[j] * w[tid + 128*j];
        dot = block_reduce_128(dot, sbuf, tid);
        if (tid == 0) { g_target[row] = dot * inv; g_rowsum[row] = 0.f; }
    } else {
        if (blockIdx.x == NROWS) {
            if (tid == 0) g_done = 0;
            // zero-fill pad rows [100000, 100096)
            uint4 z = make_uint4(0u, 0u, 0u, 0u);
            uint4* pad = reinterpret_cast<uint4*>(g_WB8 + (size_t)NCLS * DIM);
            for (int i = tid; i < (NCLSP - NCLS) * DIM / 16; i += 128) pad[i] = z;
        }
        const size_t base = ((size_t)(blockIdx.x - NROWS) * 128 + tid) * 16;
        const float4* src = reinterpret_cast<const float4*>(W + base);
        float4 v0 = src[0], v1 = src[1], v2 = src[2], v3 = src[3];
        uint4 o;
        o.x = pack4_e4m3(v0.x*WS, v0.y*WS, v0.z*WS, v0.w*WS);
        o.y = pack4_e4m3(v1.x*WS, v1.y*WS, v1.z*WS, v1.w*WS);
        o.z = pack4_e4m3(v2.x*WS, v2.y*WS, v2.z*WS, v2.w*WS);
        o.w = pack4_e4m3(v3.x*WS, v3.y*WS, v3.z*WS, v3.w*WS);
        *reinterpret_cast<uint4*>(g_WB8 + base) = o;
    }
}

// ======================= kernel 2: fp8-mma GEMM, B direct from global ========
// 296 persistent CTAs (2/SM), 256 threads / 8 warps.  Tile 128x128; warp grid
// 4(m) x 2(n), warp tile 32x64.  A resident in SMEM per segment; B fragments
// loaded straight from L1/L2 into registers (PTX m16n8k32 B layout: lane gets
// 4B at k=(lane%4)*4 and k+16, col=lane>>2).  ZERO block barriers per tile.
__global__ void __launch_bounds__(THREADS, 2) gemm_exp_kernel(float* __restrict__ out) {
    extern __shared__ __align__(16) char smem[];
    const uint32_t sb = smem_u32(smem);
    const int tid = threadIdx.x, wid = tid >> 5, lane = tid & 31;
    const int wm = wid & 3, wn = wid >> 2;     // 4(m) x 2(n)
    const int cta = blockIdx.x;
    const int t0 = (int)(((long long)cta * NTILES) / GRID);
    const int t1 = (int)(((long long)(cta + 1) * NTILES) / GRID);

    const int lrow = lane & 15, lk16 = (lane >> 4) * 16;
    const uint32_t a_lane = sb + (wm * 32 + lrow) * APITCH + lk16;
    const int col_lane = wn * 64 + (lane >> 2);      // this lane's B column base
    const int koff_lane = (lane & 3) * 4;            // b0 byte offset within k32
    const __half2 sc = __float2half2_rn(EXPS * LOG2E);

    int t = t0;
    while (t < t1) {
        const int bm = t / NBN;
        const int bn0 = t - bm * NBN;
        const int seg_end = min(t1, (bm + 1) * NBN);
        const int nt = seg_end - t;

        __syncthreads();   // prior-segment readers done before overwriting A
        const uint8_t* xa = g_xn8 + (size_t)bm * BM * DIM;
        #pragma unroll
        for (int i = 0; i < 16; i++) {
            int v = tid + THREADS * i;          // 4096 vectors = 128 rows x 32
            int r = v >> 5, kv = v & 31;
            CP_ASYNC16(sb + r * APITCH + kv * 16, xa + ((size_t)r * DIM + kv * 16));
        }
        CP_COMMIT();
        CP_WAIT0();
        __syncthreads();   // A strip visible to all warps

        uint32_t acc[2][8][2];
        #pragma unroll
        for (int fm = 0; fm < 2; fm++)
            #pragma unroll
            for (int q = 0; q < 8; q++) { acc[fm][q][0] = 0u; acc[fm][q][1] = 0u; }
        float rsum[4] = {0.f, 0.f, 0.f, 0.f};

        const uint8_t* bp = g_WB8 + ((size_t)(bn0 * BN + col_lane)) * DIM + koff_lane;

        for (int tt = 0; tt < nt; tt++) {
            const int bn = bn0 + tt;

            uint32_t Bb[2][8][2];
            uint32_t Ab[2][2][4];
            // preload ks = 0
            #pragma unroll
            for (int q = 0; q < 8; q++) {
                Bb[0][q][0] = ldg32(bp + q * 4096);
                Bb[0][q][1] = ldg32(bp + q * 4096 + 16);
            }
            ldsm4(Ab[0][0], a_lane);
            ldsm4(Ab[0][1], a_lane + 16 * APITCH);

            #pragma unroll
            for (int ks = 0; ks < 16; ks++) {
                const int cur = ks & 1, nxt = cur ^ 1;
                if (ks < 15) {
                    const int ko = (ks + 1) * 32;
                    #pragma unroll
                    for (int q = 0; q < 8; q++) {
                        Bb[nxt][q][0] = ldg32(bp + q * 4096 + ko);
                        Bb[nxt][q][1] = ldg32(bp + q * 4096 + ko + 16);
                    }
                    ldsm4(Ab[nxt][0], a_lane + ko);
                    ldsm4(Ab[nxt][1], a_lane + 16 * APITCH + ko);
                }
                #pragma unroll
                for (int fm = 0; fm < 2; fm++)
                    #pragma unroll
                    for (int q = 0; q < 8; q++)
                        mma_fp8_h(acc[fm][q], Ab[cur][fm], Bb[cur][q][0], Bb[cur][q][1]);
            }

            // ---- per-tile epilogue ----
            if (bn != NBN - 1) {
                #pragma unroll
                for (int fm = 0; fm < 2; fm++) {
                    #pragma unroll
                    for (int e = 0; e < 2; e++) {
                        __half2 hs = __float2half2_rn(0.f);
                        #pragma unroll
                        for (int q = 0; q < 8; q++) {
                            __half2 a = *reinterpret_cast<__half2*>(&acc[fm][q][e]);
                            __half2 m = __hmul2(a, sc);
                            uint32_t ex = h2ex2(*reinterpret_cast<uint32_t*>(&m));
                            hs = __hadd2(hs, *reinterpret_cast<__half2*>(&ex));
                            acc[fm][q][e] = 0u;
                        }
                        float2 fs = __half22float2(hs);
                        rsum[2*fm + e] += fs.x + fs.y;
                    }
                }
            } else {
                // tail tile: cols [99968, 100096), valid local col < 32
                const int cb = wn * 64 + (lane & 3) * 2;
                #pragma unroll
                for (int fm = 0; fm < 2; fm++) {
                    float s0 = 0.f, s1 = 0.f;
                    #pragma unroll
                    for (int q = 0; q < 8; q++) {
                        int c0 = cb + q * 8;
                        float2 f0 = h2f2(acc[fm][q][0]);
                        float2 f1 = h2f2(acc[fm][q][1]);
                        if (c0 < 32) {
                            s0 += __expf(EXPS * f0.x);
                            s1 += __expf(EXPS * f1.x);
                        }
                        if (c0 + 1 < 32) {
                            s0 += __expf(EXPS * f0.y);
                            s1 += __expf(EXPS * f1.y);
                        }
                        acc[fm][q][0] = 0u; acc[fm][q][1] = 0u;
                    }
                    rsum[2*fm] += s0; rsum[2*fm+1] += s1;
                }
            }
            bp += BN * DIM;    // next column tile: +65536 bytes
        }

        // ---- segment flush: quad-reduce, one atomic per row ----
        #pragma unroll
        for (int k = 0; k < 4; k++) {
            float v = rsum[k];
            v += __shfl_xor_sync(0xffffffffu, v, 1);
            v += __shfl_xor_sync(0xffffffffu, v, 2);
            if ((lane & 3) == 0) {
                int row = bm * BM + wm * 32 + (k >> 1) * 16 + (lane >> 2) + (k & 1) * 8;
                atomicAdd(&g_rowsum[row], v);
            }
        }
        t = seg_end;
    }

    // ---- last CTA computes the loss (finalize folded in) ----
    __threadfence();
    __syncthreads();
    __shared__ int slast;
    if (tid == 0) slast = (atomicAdd(&g_done, 1) == GRID - 1) ? 1 : 0;
    __syncthreads();
    if (slast) {
        __threadfence();
        double* sd = reinterpret_cast<double*>(smem);
        double local = 0.0;
        for (int i = tid; i < NROWS; i += THREADS) {
            float tg  = g_target[i];
            float num = S_SCALE * (tg - MARGIN);
            float denom = __expf(num) + g_rowsum[i] - __expf(S_SCALE * tg);
            local += (double)num - (double)__logf(denom);
        }
        sd[tid] = local;
        __syncthreads();
        for (int s = THREADS / 2; s > 0; s >>= 1) {
            if (tid < s) sd[tid] += sd[tid + s];
            __syncthreads();
        }
        if (tid == 0) out[0] = (float)(-sd[0] / (double)NROWS);
    }
}

// ======================= launch ==============================================
extern "C" void kernel_launch(void* const* d_in, const int* in_sizes, int n_in,
                              void* d_out, int out_size) {
    const float* x      = (const float*)d_in[0];
    const int*   labels = (const int*)d_in[1];
    const float* W      = (const float*)d_in[2];
    float* out = (float*)d_out;

    cudaFuncSetAttribute(gemm_exp_kernel,
                         cudaFuncAttributeMaxDynamicSharedMemorySize, SMEM_BYTES);

    prep_kernel<<<NROWS + 25000, 128>>>(x, labels, W);
    gemm_exp_kernel<<<GRID, THREADS, SMEM_BYTES>>>(out);
}

// round 17
// speedup vs baseline: 1.8731x; 1.8731x over previous
#include <cuda_runtime.h>
#include <cuda_bf16.h>
#include <cuda_fp16.h>
#include <cuda_fp8.h>
#include <cstdint>

#define NROWS 4096
#define DIM   512
#define NCLS  100000
#define NCLSP 100096         // padded rows in g_WB8 (pad zero-filled)
#define NBM   32
#define NBN   782            // ceil(100000/128)
#define NTILES (NBM * NBN)   // 25024
#define GRID  296            // 2 CTAs per SM
#define THREADS 256
#define S_SCALE 30.0f
#define MARGIN  0.4f
#define XS 8.0f              // fp8 scale for xn
#define WS 32.0f             // fp8 scale for W
#define EXPS (S_SCALE / (XS * WS))
#define LOG2E 1.4426950408889634f

// ---------------- scratch (module-static device memory: allowed) ------------
__device__ __align__(128) uint8_t g_WB8[(size_t)NCLSP * DIM];  // e4m3 W*32 (+pad)
__device__ __align__(128) uint8_t g_xn8[(size_t)NROWS * DIM];  // e4m3 xn*8
__device__ float g_rowsum[NROWS];
__device__ float g_target[NROWS];
__device__ int   g_done;

// ---------------- PTX helpers (sm_80/89-era, safe on sm_103) ----------------
__device__ __forceinline__ uint32_t smem_u32(const void* p) {
    uint32_t a;
    asm("{ .reg .u64 t; cvta.to.shared.u64 t, %1; cvt.u32.u64 %0, t; }" : "=r"(a) : "l"(p));
    return a;
}
#define CP_ASYNC16(dst, src) \
    asm volatile("cp.async.cg.shared.global [%0], [%1], 16;" :: "r"(dst), "l"(src) : "memory")
#define CP_COMMIT()  asm volatile("cp.async.commit_group;" ::: "memory")
#define CP_WAIT0()   asm volatile("cp.async.wait_group 0;" ::: "memory")

__device__ __forceinline__ void ldsm4(uint32_t* r, uint32_t addr) {
    asm volatile("ldmatrix.sync.aligned.m8n8.x4.shared.b16 {%0,%1,%2,%3}, [%4];"
                 : "=r"(r[0]), "=r"(r[1]), "=r"(r[2]), "=r"(r[3]) : "r"(addr));
}
__device__ __forceinline__ void mma_fp8_h(uint32_t* c, const uint32_t* a,
                                          uint32_t b0, uint32_t b1) {
    asm volatile("mma.sync.aligned.m16n8k32.row.col.f16.e4m3.e4m3.f16 "
                 "{%0,%1}, {%2,%3,%4,%5}, {%6,%7}, {%0,%1};"
                 : "+r"(c[0]), "+r"(c[1])
                 : "r"(a[0]), "r"(a[1]), "r"(a[2]), "r"(a[3]), "r"(b0), "r"(b1));
}
__device__ __forceinline__ uint32_t h2ex2(uint32_t x) {
    uint32_t r;
    asm("ex2.approx.f16x2 %0, %1;" : "=r"(r) : "r"(x));
    return r;
}
__device__ __forceinline__ uint32_t pack4_e4m3(float a0, float a1, float a2, float a3) {
    __nv_fp8x2_e4m3 lo(make_float2(a0, a1));
    __nv_fp8x2_e4m3 hi(make_float2(a2, a3));
    return (uint32_t)lo.__x | ((uint32_t)hi.__x << 16);
}
__device__ __forceinline__ float2 h2f2(uint32_t r) {
    return __half22float2(*reinterpret_cast<__half2*>(&r));
}

// ---------------- tiling (pitches in BYTES) -----------------------------------
#define BM 128
#define BN 128
#define CHUNK_B 128
#define NCHUNK  4
#define APITCH 528           // 132 words == 4 mod 32 (ldsm conflict-free)
#define BPITCH 144           // 36 words  == 4 mod 32

#define A_BYTES       (BM * APITCH)                  // 67584
#define B_STAGE_BYTES (BN * BPITCH)                  // 18432
#define B_OFF         A_BYTES
#define SMEM_BYTES    (B_OFF + 2 * B_STAGE_BYTES)    // 104448

// ======================= kernel 1: prep ======================================
__device__ __forceinline__ float block_reduce_128(float v, float* sbuf, int tid) {
    #pragma unroll
    for (int o = 16; o > 0; o >>= 1) v += __shfl_xor_sync(0xffffffffu, v, o);
    if ((tid & 31) == 0) sbuf[tid >> 5] = v;
    __syncthreads();
    float r = sbuf[0] + sbuf[1] + sbuf[2] + sbuf[3];
    __syncthreads();
    return r;
}

__global__ void prep_kernel(const float* __restrict__ x,
                            const int* __restrict__ labels_raw,
                            const float* __restrict__ W) {
    __shared__ float sbuf[4];
    const int tid = threadIdx.x;
    if (blockIdx.x < NROWS) {
        const int row = blockIdx.x;
        const float* xr = x + (size_t)row * DIM;
        float v[4]; float ss = 0.f;
        #pragma unroll
        for (int j = 0; j < 4; j++) { v[j] = xr[tid + 128*j]; ss += v[j]*v[j]; }
        ss = block_reduce_128(ss, sbuf, tid);
        float inv = rsqrtf(ss);
        #pragma unroll
        for (int j = 0; j < 4; j++)
            g_xn8[(size_t)row * DIM + tid + 128*j] =
                __nv_fp8_e4m3(v[j] * inv * XS).__x;

        bool is64 = (labels_raw[1] == 0 && labels_raw[3] == 0 &&
                     labels_raw[5] == 0 && labels_raw[7] == 0);
        int lab = is64 ? labels_raw[2*row] : labels_raw[row];
        const float* w = W + (size_t)lab * DIM;
        float dot = 0.f;
        #pragma unroll
        for (int j = 0; j < 4; j++) dot += v[j] * w[tid + 128*j];
        dot = block_reduce_128(dot, sbuf, tid);
        if (tid == 0) { g_target[row] = dot * inv; g_rowsum[row] = 0.f; }
    } else {
        if (blockIdx.x == NROWS) {
            if (tid == 0) g_done = 0;
            // zero-fill pad rows [100000, 100096) so B loads need no clamp
            uint4 z = make_uint4(0u, 0u, 0u, 0u);
            uint4* pad = reinterpret_cast<uint4*>(g_WB8 + (size_t)NCLS * DIM);
            for (int i = tid; i < (NCLSP - NCLS) * DIM / 16; i += 128) pad[i] = z;
        }
        const size_t base = ((size_t)(blockIdx.x - NROWS) * 128 + tid) * 16;
        const float4* src = reinterpret_cast<const float4*>(W + base);
        float4 v0 = src[0], v1 = src[1], v2 = src[2], v3 = src[3];
        uint4 o;
        o.x = pack4_e4m3(v0.x*WS, v0.y*WS, v0.z*WS, v0.w*WS);
        o.y = pack4_e4m3(v1.x*WS, v1.y*WS, v1.z*WS, v1.w*WS);
        o.z = pack4_e4m3(v2.x*WS, v2.y*WS, v2.z*WS, v2.w*WS);
        o.w = pack4_e4m3(v3.x*WS, v3.y*WS, v3.z*WS, v3.w*WS);
        *reinterpret_cast<uint4*>(g_WB8 + base) = o;
    }
}

// ======================= kernel 2: fp8-mma GEMM + exp rowsum =================
// 296 persistent CTAs (2/SM), 256 threads / 8 warps each.  Tile 128x128;
// warp grid 4(m) x 2(n), warp tile 32x64.  Sibling CTA hides barrier/epilogue
// bubbles.  Static 4-chunk tile body (stage = c&1), 2-stage cp.async pipeline,
// one barrier per chunk.  B rows unclamped (g_WB8 padded to 100096 rows).
__device__ __forceinline__ void issue_b_chunk(uint32_t bs_dst, int bn, int k0, int tid) {
    #pragma unroll
    for (int i = 0; i < 4; i++) {
        int v = tid + THREADS * i;              // 1024 vectors = 128 rows x 8
        int r = v >> 3, kv = v & 7;
        const void* src = g_WB8 + ((size_t)(bn * BN + r) * DIM + k0 + kv * 16);
        CP_ASYNC16(bs_dst + r * BPITCH + kv * 16, src);
    }
}

__global__ void __launch_bounds__(THREADS, 2) gemm_exp_kernel(float* __restrict__ out) {
    extern __shared__ __align__(16) char smem[];
    const uint32_t sb = smem_u32(smem);
    const int tid = threadIdx.x, wid = tid >> 5, lane = tid & 31;
    const int wm = wid & 3, wn = wid >> 2;     // 4(m) x 2(n)
    const int cta = blockIdx.x;
    const int t0 = (int)(((long long)cta * NTILES) / GRID);
    const int t1 = (int)(((long long)(cta + 1) * NTILES) / GRID);

    const int lrow = lane & 15, lk16 = (lane >> 4) * 16;
    const uint32_t a_lane = sb + (wm * 32 + lrow) * APITCH + lk16;
    const uint32_t b_lane = sb + B_OFF + (wn * 64 + lrow) * BPITCH + lk16;
    const __half2 sc = __float2half2_rn(EXPS * LOG2E);

    int t = t0;
    while (t < t1) {
        const int bm = t / NBN;
        const int bn0 = t - bm * NBN;
        const int seg_end = min(t1, (bm + 1) * NBN);
        const int nt = seg_end - t;

        __syncthreads();   // prior-segment readers done before overwriting SMEM
        // ---- prologue: one group = {A strip, chunk0 -> stage 0} ----
        const uint8_t* xa = g_xn8 + (size_t)bm * BM * DIM;
        #pragma unroll
        for (int i = 0; i < 16; i++) {
            int v = tid + THREADS * i;          // 4096 vectors = 128 rows x 32
            int r = v >> 5, kv = v & 31;
            CP_ASYNC16(sb + r * APITCH + kv * 16, xa + ((size_t)r * DIM + kv * 16));
        }
        issue_b_chunk(sb + B_OFF, bn0, 0, tid);
        CP_COMMIT();

        uint32_t acc[2][8][2];
        #pragma unroll
        for (int fm = 0; fm < 2; fm++)
            #pragma unroll
            for (int q = 0; q < 8; q++) { acc[fm][q][0] = 0u; acc[fm][q][1] = 0u; }
        float rsum[4] = {0.f, 0.f, 0.f, 0.f};

        for (int tt = 0; tt < nt; tt++) {
            const int bn = bn0 + tt;
            const bool last_tile = (tt == nt - 1);

            #pragma unroll
            for (int c = 0; c < NCHUNK; c++) {
                CP_WAIT0();        // chunk c of this tile has arrived
                __syncthreads();   // publish it; certify stage (c+1)&1 free
                if (c < 3) {
                    issue_b_chunk(sb + B_OFF + ((c + 1) & 1) * B_STAGE_BYTES,
                                  bn, (c + 1) * CHUNK_B, tid);
                    CP_COMMIT();
                } else if (!last_tile) {
                    issue_b_chunk(sb + B_OFF, bn + 1, 0, tid);   // stage 0
                    CP_COMMIT();
                }

                const uint32_t bch = b_lane + (c & 1) * B_STAGE_BYTES;
                const uint32_t ach = a_lane + c * CHUNK_B;
                #pragma unroll
                for (int ks = 0; ks < 4; ks++) {
                    uint32_t Af[2][4], Bf[4][4];
                    #pragma unroll
                    for (int fm = 0; fm < 2; fm++)
                        ldsm4(Af[fm], ach + fm * 16 * APITCH + ks * 32);
                    #pragma unroll
                    for (int f = 0; f < 4; f++)
                        ldsm4(Bf[f], bch + f * 16 * BPITCH + ks * 32);
                    #pragma unroll
                    for (int fm = 0; fm < 2; fm++)
                        #pragma unroll
                        for (int f = 0; f < 4; f++) {
                            mma_fp8_h(acc[fm][2*f],   Af[fm], Bf[f][0], Bf[f][2]);
                            mma_fp8_h(acc[fm][2*f+1], Af[fm], Bf[f][1], Bf[f][3]);
                        }
                }

                // ---- per-tile epilogue (static: only at c == 3) ----
                if (c == 3) {
                    if (bn != NBN - 1) {
                        #pragma unroll
                        for (int fm = 0; fm < 2; fm++) {
                            #pragma unroll
                            for (int e = 0; e < 2; e++) {
                                // two interleaved chains halve the dep latency
                                __half2 hs0 = __float2half2_rn(0.f);
                                __half2 hs1 = __float2half2_rn(0.f);
                                #pragma unroll
                                for (int q = 0; q < 8; q += 2) {
                                    __half2 a0 = *reinterpret_cast<__half2*>(&acc[fm][q][e]);
                                    __half2 a1 = *reinterpret_cast<__half2*>(&acc[fm][q+1][e]);
                                    __half2 m0 = __hmul2(a0, sc);
                                    __half2 m1 = __hmul2(a1, sc);
                                    uint32_t e0 = h2ex2(*reinterpret_cast<uint32_t*>(&m0));
                                    uint32_t e1 = h2ex2(*reinterpret_cast<uint32_t*>(&m1));
                                    hs0 = __hadd2(hs0, *reinterpret_cast<__half2*>(&e0));
                                    hs1 = __hadd2(hs1, *reinterpret_cast<__half2*>(&e1));
                                    acc[fm][q][e] = 0u; acc[fm][q+1][e] = 0u;
                                }
                                float2 f0 = __half22float2(hs0);
                                float2 f1 = __half22float2(hs1);
                                rsum[2*fm + e] += (f0.x + f0.y) + (f1.x + f1.y);
                            }
                        }
                    } else {
                        // tail tile: cols [99968, 100096), valid local col < 32
                        const int cb = wn * 64 + (lane & 3) * 2;
                        #pragma unroll
                        for (int fm = 0; fm < 2; fm++) {
                            float s0 = 0.f, s1 = 0.f;
                            #pragma unroll
                            for (int q = 0; q < 8; q++) {
                                int c0 = cb + q * 8;
                                float2 f0 = h2f2(acc[fm][q][0]);
                                float2 f1 = h2f2(acc[fm][q][1]);
                                if (c0 < 32) {
                                    s0 += __expf(EXPS * f0.x);
                                    s1 += __expf(EXPS * f1.x);
                                }
                                if (c0 + 1 < 32) {
                                    s0 += __expf(EXPS * f0.y);
                                    s1 += __expf(EXPS * f1.y);
                                }
                                acc[fm][q][0] = 0u; acc[fm][q][1] = 0u;
                            }
                            rsum[2*fm] += s0; rsum[2*fm+1] += s1;
                        }
                    }
                }
            }
        }

        // ---- segment flush: quad-reduce, one atomic per row ----
        #pragma unroll
        for (int k = 0; k < 4; k++) {
            float v = rsum[k];
            v += __shfl_xor_sync(0xffffffffu, v, 1);
            v += __shfl_xor_sync(0xffffffffu, v, 2);
            if ((lane & 3) == 0) {
                int row = bm * BM + wm * 32 + (k >> 1) * 16 + (lane >> 2) + (k & 1) * 8;
                atomicAdd(&g_rowsum[row], v);
            }
        }
        t = seg_end;
    }

    // ---- last CTA computes the loss (finalize folded in) ----
    __threadfence();
    __syncthreads();
    __shared__ int slast;
    if (tid == 0) slast = (atomicAdd(&g_done, 1) == GRID - 1) ? 1 : 0;
    __syncthreads();
    if (slast) {
        __threadfence();
        double* sd = reinterpret_cast<double*>(smem);
        double local = 0.0;
        for (int i = tid; i < NROWS; i += THREADS) {
            float tg  = g_target[i];
            float num = S_SCALE * (tg - MARGIN);
            float denom = __expf(num) + g_rowsum[i] - __expf(S_SCALE * tg);
            local += (double)num - (double)__logf(denom);
        }
        sd[tid] = local;
        __syncthreads();
        for (int s = THREADS / 2; s > 0; s >>= 1) {
            if (tid < s) sd[tid] += sd[tid + s];
            __syncthreads();
        }
        if (tid == 0) out[0] = (float)(-sd[0] / (double)NROWS);
    }
}

// ======================= launch ==============================================
extern "C" void kernel_launch(void* const* d_in, const int* in_sizes, int n_in,
                              void* d_out, int out_size) {
    const float* x      = (const float*)d_in[0];
    const int*   labels = (const int*)d_in[1];
    const float* W      = (const float*)d_in[2];
    float* out = (float*)d_out;

    cudaFuncSetAttribute(gemm_exp_kernel,
                         cudaFuncAttributeMaxDynamicSharedMemorySize, SMEM_BYTES);

    prep_kernel<<<NROWS + 25000, 128>>>(x, labels, W);
    gemm_exp_kernel<<<GRID, THREADS, SMEM_BYTES>>>(out);
}